// round 11
// baseline (speedup 1.0000x reference)
#include <cuda_runtime.h>

#define NM 1024
#define HH 256
#define WW 256
#define HWsz 65536
#define MCAP 256

// Scratch (allocation-free: __device__ globals)
__device__ float g_boxes[NM * 4];
__device__ int   g_valid[NM];
__device__ float g_gated[NM];

// ---------------------------------------------------------------------------
// Kernel A: per-mask stats. Exact R3 shape (31 regs, 45.6us @ 6.07TB/s).
// ---------------------------------------------------------------------------
__global__ __launch_bounds__(256) void stats_kernel(const float* __restrict__ logits,
                                                    const float* __restrict__ iou) {
    int n = blockIdx.x;
    const float4* p = (const float4*)(logits + (size_t)n * HWsz);

    int hi = 0, lo = 0;
    int minX = WW, maxX = -1, minY = HH, maxY = -1;

    for (int k = threadIdx.x; k < HWsz / 8; k += 256) {
        float4 a = p[k];
        float4 b = p[k + HWsz / 8];
        {
            int lin = k << 2;
            int y = lin >> 8, x = lin & 255;
            hi += (a.x > 1.0f) + (a.y > 1.0f) + (a.z > 1.0f) + (a.w > 1.0f);
            lo += (a.x > -1.0f) + (a.y > -1.0f) + (a.z > -1.0f) + (a.w > -1.0f);
            unsigned m = (a.x > 0.0f ? 1u : 0u) | (a.y > 0.0f ? 2u : 0u) |
                         (a.z > 0.0f ? 4u : 0u) | (a.w > 0.0f ? 8u : 0u);
            if (m) {
                minY = min(minY, y); maxY = max(maxY, y);
                minX = min(minX, x + (__ffs(m) - 1));
                maxX = max(maxX, x + (31 - __clz(m)));
            }
        }
        {
            int lin = (k + HWsz / 8) << 2;
            int y = lin >> 8, x = lin & 255;
            hi += (b.x > 1.0f) + (b.y > 1.0f) + (b.z > 1.0f) + (b.w > 1.0f);
            lo += (b.x > -1.0f) + (b.y > -1.0f) + (b.z > -1.0f) + (b.w > -1.0f);
            unsigned m = (b.x > 0.0f ? 1u : 0u) | (b.y > 0.0f ? 2u : 0u) |
                         (b.z > 0.0f ? 4u : 0u) | (b.w > 0.0f ? 8u : 0u);
            if (m) {
                minY = min(minY, y); maxY = max(maxY, y);
                minX = min(minX, x + (__ffs(m) - 1));
                maxX = max(maxX, x + (31 - __clz(m)));
            }
        }
    }

    #pragma unroll
    for (int off = 16; off; off >>= 1) {
        hi += __shfl_down_sync(0xFFFFFFFFu, hi, off);
        lo += __shfl_down_sync(0xFFFFFFFFu, lo, off);
        minX = min(minX, __shfl_down_sync(0xFFFFFFFFu, minX, off));
        maxX = max(maxX, __shfl_down_sync(0xFFFFFFFFu, maxX, off));
        minY = min(minY, __shfl_down_sync(0xFFFFFFFFu, minY, off));
        maxY = max(maxY, __shfl_down_sync(0xFFFFFFFFu, maxY, off));
    }

    __shared__ int s[6][8];
    int wid = threadIdx.x >> 5, lane = threadIdx.x & 31;
    if (lane == 0) {
        s[0][wid] = hi; s[1][wid] = lo;
        s[2][wid] = minX; s[3][wid] = maxX;
        s[4][wid] = minY; s[5][wid] = maxY;
    }
    __syncthreads();
    if (threadIdx.x == 0) {
        int Hc = 0, Lc = 0, mX = WW, MX = -1, mY = HH, MY = -1;
        #pragma unroll
        for (int w = 0; w < 8; w++) {
            Hc += s[0][w]; Lc += s[1][w];
            mX = min(mX, s[2][w]); MX = max(MX, s[3][w]);
            mY = min(mY, s[4][w]); MY = max(MY, s[5][w]);
        }
        float stab = (float)Hc / fmaxf((float)Lc, 1.0f);
        float sc = iou[n];
        g_valid[n] = (sc > 0.88f) && (stab >= 0.95f);
        float x0, y0, x1, y1;
        if (MY < 0) { x0 = y0 = x1 = y1 = 0.0f; }
        else { x0 = (float)mX; y0 = (float)mY; x1 = (float)MX; y1 = (float)MY; }
        g_boxes[n * 4 + 0] = x0;
        g_boxes[n * 4 + 1] = y0;
        g_boxes[n * 4 + 2] = x1;
        g_boxes[n * 4 + 3] = y1;
    }
}

// ---------------------------------------------------------------------------
// Kernel B: standalone bitmatrix NMS (single block, 256 threads).
// ---------------------------------------------------------------------------
__global__ __launch_bounds__(256) void nms_kernel(const float* __restrict__ iou,
                                                  float* __restrict__ out,
                                                  int write_tail) {
    __shared__ float  sScore[NM];
    __shared__ float4 sBox[NM];
    __shared__ short  sIdx[NM];
    __shared__ short  sOrder[NM];
    __shared__ unsigned char sKO[NM];
    __shared__ unsigned sMat[MCAP][MCAP / 32];
    __shared__ short sKeepList[MCAP];
    __shared__ int sM, sCnt;

    int t = threadIdx.x;
    if (t == 0) { sM = 0; sCnt = 0; }
    for (int i = t; i < NM; i += 256) {
        sScore[i] = iou[i];
        sBox[i] = make_float4(g_boxes[i * 4 + 0], g_boxes[i * 4 + 1],
                              g_boxes[i * 4 + 2], g_boxes[i * 4 + 3]);
        sKO[i] = 0;
    }
    __syncthreads();
    for (int i = t; i < NM; i += 256) {
        if (g_valid[i]) {
            int pos = atomicAdd(&sM, 1);
            sIdx[pos] = (short)i;
        }
    }
    __syncthreads();
    int M = sM;

    // rank-sort valid entries (stable: ties -> lower original index first)
    for (int s0 = t; s0 < M; s0 += 256) {
        int i = sIdx[s0];
        float ki = sScore[i];
        int rank = 0;
        for (int u = 0; u < M; u++) {
            int j = sIdx[u];
            float kj = sScore[j];
            rank += (kj > ki) || (kj == ki && j < i);
        }
        sOrder[rank] = (short)i;
    }
    __syncthreads();

    if (M <= MCAP) {
        int nw = (M + 31) >> 5;
        for (int e = t; e < M * nw; e += 256) {
            int i = e / nw, w = e % nw;
            float4 bi = sBox[sOrder[i]];
            float areaA = fmaxf(bi.z - bi.x, 0.0f) * fmaxf(bi.w - bi.y, 0.0f);
            unsigned bits = 0;
            int jbase = w << 5;
            #pragma unroll 8
            for (int b = 0; b < 32; b++) {
                int j = jbase + b;
                if (j < M && j > i) {
                    float4 bj = sBox[sOrder[j]];
                    float x0 = fmaxf(bi.x, bj.x), y0 = fmaxf(bi.y, bj.y);
                    float x1 = fminf(bi.z, bj.z), y1 = fminf(bi.w, bj.w);
                    float inter = fmaxf(x1 - x0, 0.0f) * fmaxf(y1 - y0, 0.0f);
                    float areaB = fmaxf(bj.z - bj.x, 0.0f) * fmaxf(bj.w - bj.y, 0.0f);
                    float v = inter / fmaxf(areaA + areaB - inter, 1e-6f);
                    if (v > 0.7f) bits |= (1u << b);
                }
            }
            sMat[i][w] = bits;
        }
        __syncthreads();

        if (t == 0) {
            unsigned alive[MCAP / 32];
            #pragma unroll
            for (int w = 0; w < MCAP / 32; w++) {
                int lo32 = w << 5;
                if (M >= lo32 + 32) alive[w] = 0xFFFFFFFFu;
                else if (M <= lo32) alive[w] = 0u;
                else alive[w] = (1u << (M - lo32)) - 1u;
            }
            int cnt = 0;
            int nwv = (M + 31) >> 5;
            for (int i = 0; i < M; i++) {
                if (!((alive[i >> 5] >> (i & 31)) & 1u)) continue;
                sKeepList[cnt++] = (short)i;
                for (int w = 0; w < nwv; w++) alive[w] &= ~sMat[i][w];
            }
            sCnt = cnt;
        }
        __syncthreads();
        for (int r = t; r < sCnt; r += 256)
            sKO[sOrder[sKeepList[r]]] = 1;
        __syncthreads();
    } else {
        // Fallback: warp-0 register-bitmask greedy (M up to 1024)
        if (t < 32) {
            int lane2 = t;
            unsigned alive = 0;
            #pragma unroll
            for (int b = 0; b < 32; b++)
                if (b * 32 + lane2 < M) alive |= (1u << b);
            unsigned keepbits = 0;
            while (true) {
                int cand = alive ? ((__ffs(alive) - 1) * 32 + lane2) : 0x7FFFFFFF;
                #pragma unroll
                for (int off = 16; off; off >>= 1)
                    cand = min(cand, __shfl_xor_sync(0xFFFFFFFFu, cand, off));
                if (cand == 0x7FFFFFFF) break;
                int i = cand;
                if ((i & 31) == lane2) {
                    keepbits |= (1u << (i >> 5));
                    alive &= ~(1u << (i >> 5));
                }
                float4 bi = sBox[sOrder[i]];
                float areaA = fmaxf(bi.z - bi.x, 0.0f) * fmaxf(bi.w - bi.y, 0.0f);
                unsigned m = alive;
                while (m) {
                    int b = __ffs(m) - 1; m &= m - 1;
                    int p2 = b * 32 + lane2;
                    float4 bj = sBox[sOrder[p2]];
                    float x0 = fmaxf(bi.x, bj.x), y0 = fmaxf(bi.y, bj.y);
                    float x1 = fminf(bi.z, bj.z), y1 = fminf(bi.w, bj.w);
                    float inter = fmaxf(x1 - x0, 0.0f) * fmaxf(y1 - y0, 0.0f);
                    float areaB = fmaxf(bj.z - bj.x, 0.0f) * fmaxf(bj.w - bj.y, 0.0f);
                    float v = inter / fmaxf(areaA + areaB - inter, 1e-6f);
                    if (v > 0.7f) alive &= ~(1u << b);
                }
            }
            while (keepbits) {
                int b = __ffs(keepbits) - 1; keepbits &= keepbits - 1;
                sKO[sOrder[b * 32 + lane2]] = 1;
            }
        }
        __syncthreads();
    }

    size_t base = (size_t)NM * HWsz;
    for (int i = t; i < NM; i += 256) {
        float k = sKO[i] ? 1.0f : 0.0f;
        g_gated[i] = k * sScore[i];
        if (write_tail) {
            out[base + i] = k;
            float4 b = sBox[i];
            out[base + NM + (size_t)i * 4 + 0] = b.x;
            out[base + NM + (size_t)i * 4 + 1] = b.y;
            out[base + NM + (size_t)i * 4 + 2] = b.z;
            out[base + NM + (size_t)i * 4 + 3] = b.w;
        }
    }
}

// ---------------------------------------------------------------------------
// Kernel C: output. Exact R10 shape (47.5us @ 6.2TB/s combined, stcs/ldcs).
// ---------------------------------------------------------------------------
__global__ __launch_bounds__(256) void out_kernel(const float* __restrict__ logits,
                                                  float* __restrict__ out) {
    int n = blockIdx.y;
    float g = g_gated[n];
    size_t base = (size_t)n * HWsz;
    int i0 = blockIdx.x * 1024 + threadIdx.x;   // float4 index, 4 chunks of 256
    float4* o = (float4*)(out + base);
    if (g == 0.0f) {
        float4 z = make_float4(0.0f, 0.0f, 0.0f, 0.0f);
        #pragma unroll
        for (int j = 0; j < 4; j++) __stcs(&o[i0 + j * 256], z);
        return;
    }
    const float4* p = (const float4*)(logits + base);
    float4 v[4];
    #pragma unroll
    for (int j = 0; j < 4; j++) v[j] = __ldcs(&p[i0 + j * 256]);
    #pragma unroll
    for (int j = 0; j < 4; j++) {
        v[j].x = g / (1.0f + __expf(-v[j].x));
        v[j].y = g / (1.0f + __expf(-v[j].y));
        v[j].z = g / (1.0f + __expf(-v[j].z));
        v[j].w = g / (1.0f + __expf(-v[j].w));
        __stcs(&o[i0 + j * 256], v[j]);
    }
}

extern "C" void kernel_launch(void* const* d_in, const int* in_sizes, int n_in,
                              void* d_out, int out_size) {
    const float* logits = (const float*)d_in[0];  // [1024,256,256]
    const float* iou    = (const float*)d_in[1];  // [1024]
    float* out = (float*)d_out;

    int write_tail = (out_size >= NM * HWsz + NM + NM * 4) ? 1 : 0;

    stats_kernel<<<NM, 256>>>(logits, iou);
    nms_kernel<<<1, 256>>>(iou, out, write_tail);
    dim3 grid(16, NM);
    out_kernel<<<grid, 256>>>(logits, out);
}

// round 13
// speedup vs baseline: 1.2497x; 1.2497x over previous
#include <cuda_runtime.h>

#define NM 1024
#define HH 256
#define WW 256
#define HWsz 65536
#define MCAP 256

// Scratch (allocation-free: __device__ globals)
__device__ float g_boxes[NM * 4];
__device__ int   g_valid[NM];
__device__ float g_gated[NM];

// ---------------------------------------------------------------------------
// Kernel A: per-mask stats. Proven R3 shape (31 regs, ~45-53us read-only).
// ---------------------------------------------------------------------------
__global__ __launch_bounds__(256) void stats_kernel(const float* __restrict__ logits,
                                                    const float* __restrict__ iou) {
    int n = blockIdx.x;
    const float4* p = (const float4*)(logits + (size_t)n * HWsz);

    int hi = 0, lo = 0;
    int minX = WW, maxX = -1, minY = HH, maxY = -1;

    for (int k = threadIdx.x; k < HWsz / 8; k += 256) {
        float4 a = p[k];
        float4 b = p[k + HWsz / 8];
        {
            int lin = k << 2;
            int y = lin >> 8, x = lin & 255;
            hi += (a.x > 1.0f) + (a.y > 1.0f) + (a.z > 1.0f) + (a.w > 1.0f);
            lo += (a.x > -1.0f) + (a.y > -1.0f) + (a.z > -1.0f) + (a.w > -1.0f);
            unsigned m = (a.x > 0.0f ? 1u : 0u) | (a.y > 0.0f ? 2u : 0u) |
                         (a.z > 0.0f ? 4u : 0u) | (a.w > 0.0f ? 8u : 0u);
            if (m) {
                minY = min(minY, y); maxY = max(maxY, y);
                minX = min(minX, x + (__ffs(m) - 1));
                maxX = max(maxX, x + (31 - __clz(m)));
            }
        }
        {
            int lin = (k + HWsz / 8) << 2;
            int y = lin >> 8, x = lin & 255;
            hi += (b.x > 1.0f) + (b.y > 1.0f) + (b.z > 1.0f) + (b.w > 1.0f);
            lo += (b.x > -1.0f) + (b.y > -1.0f) + (b.z > -1.0f) + (b.w > -1.0f);
            unsigned m = (b.x > 0.0f ? 1u : 0u) | (b.y > 0.0f ? 2u : 0u) |
                         (b.z > 0.0f ? 4u : 0u) | (b.w > 0.0f ? 8u : 0u);
            if (m) {
                minY = min(minY, y); maxY = max(maxY, y);
                minX = min(minX, x + (__ffs(m) - 1));
                maxX = max(maxX, x + (31 - __clz(m)));
            }
        }
    }

    #pragma unroll
    for (int off = 16; off; off >>= 1) {
        hi += __shfl_down_sync(0xFFFFFFFFu, hi, off);
        lo += __shfl_down_sync(0xFFFFFFFFu, lo, off);
        minX = min(minX, __shfl_down_sync(0xFFFFFFFFu, minX, off));
        maxX = max(maxX, __shfl_down_sync(0xFFFFFFFFu, maxX, off));
        minY = min(minY, __shfl_down_sync(0xFFFFFFFFu, minY, off));
        maxY = max(maxY, __shfl_down_sync(0xFFFFFFFFu, maxY, off));
    }

    __shared__ int s[6][8];
    int wid = threadIdx.x >> 5, lane = threadIdx.x & 31;
    if (lane == 0) {
        s[0][wid] = hi; s[1][wid] = lo;
        s[2][wid] = minX; s[3][wid] = maxX;
        s[4][wid] = minY; s[5][wid] = maxY;
    }
    __syncthreads();
    if (threadIdx.x == 0) {
        int Hc = 0, Lc = 0, mX = WW, MX = -1, mY = HH, MY = -1;
        #pragma unroll
        for (int w = 0; w < 8; w++) {
            Hc += s[0][w]; Lc += s[1][w];
            mX = min(mX, s[2][w]); MX = max(MX, s[3][w]);
            mY = min(mY, s[4][w]); MY = max(MY, s[5][w]);
        }
        float stab = (float)Hc / fmaxf((float)Lc, 1.0f);
        float sc = iou[n];
        g_valid[n] = (sc > 0.88f) && (stab >= 0.95f);
        float x0, y0, x1, y1;
        if (MY < 0) { x0 = y0 = x1 = y1 = 0.0f; }
        else { x0 = (float)mX; y0 = (float)mY; x1 = (float)MX; y1 = (float)MY; }
        g_boxes[n * 4 + 0] = x0;
        g_boxes[n * 4 + 1] = y0;
        g_boxes[n * 4 + 2] = x1;
        g_boxes[n * 4 + 3] = y1;
    }
}

// ---------------------------------------------------------------------------
// Kernel B: 1025 blocks. Block 0 = bitmatrix NMS (~40us). Blocks 1..1024 =
// streaming zero-fill for INVALID masks (~235MB stcs, ~43us) running
// concurrently on the other SMs. NMS latency hides behind the write stream.
// ---------------------------------------------------------------------------
__global__ __launch_bounds__(256) void nmszero_kernel(const float* __restrict__ iou,
                                                      float* __restrict__ out,
                                                      int write_tail) {
    __shared__ short  sIdxV[MCAP];      // compacted valid original indices
    __shared__ float  sScoreV[MCAP];
    __shared__ short  sOrder[NM];       // sorted->original (2KB; fallback uses NM)
    __shared__ float4 sBoxS[MCAP];      // boxes by sorted position
    __shared__ unsigned sMat[MCAP][MCAP / 32];  // 8KB suppression bitmatrix
    __shared__ short sKeepList[MCAP];
    __shared__ unsigned char sKO[NM];   // keep by original index
    __shared__ int sM, sCnt;

    int t = threadIdx.x;

    if (blockIdx.x != 0) {
        // ---- streaming zero-fill for one invalid mask ----
        int n = blockIdx.x - 1;
        if (g_valid[n]) return;          // valid masks handled by kernel C
        float4* o = (float4*)(out + (size_t)n * HWsz);
        const float4 z = make_float4(0.0f, 0.0f, 0.0f, 0.0f);
        #pragma unroll 4
        for (int j = 0; j < 64; j++)
            __stcs(&o[j * 256 + t], z);
        return;
    }

    // =========================== NMS (block 0) =============================
    if (t == 0) { sM = 0; sCnt = 0; }
    for (int i = t; i < NM; i += 256) sKO[i] = 0;
    __syncthreads();

    // compact valid entries
    for (int i = t; i < NM; i += 256) {
        if (g_valid[i]) {
            int pos = atomicAdd(&sM, 1);
            if (pos < MCAP) { sIdxV[pos] = (short)i; sScoreV[pos] = iou[i]; }
        }
    }
    __syncthreads();
    int M = sM;

    if (M <= MCAP) {
        // rank-sort valid entries (stable: ties -> lower original index first)
        if (t < M) {
            int i = sIdxV[t];
            float ki = sScoreV[t];
            int rank = 0;
            for (int u = 0; u < M; u++) {
                int j = sIdxV[u];
                float kj = sScoreV[u];
                rank += (kj > ki) || (kj == ki && j < i);
            }
            sOrder[rank] = (short)i;
        }
        __syncthreads();
        // stage boxes by sorted position
        if (t < M) {
            int orig = sOrder[t];
            sBoxS[t] = make_float4(g_boxes[orig * 4 + 0], g_boxes[orig * 4 + 1],
                                   g_boxes[orig * 4 + 2], g_boxes[orig * 4 + 3]);
        }
        __syncthreads();

        // suppression bitmatrix: row i, bit j set if j>i and IoU>0.7
        int nw = (M + 31) >> 5;
        for (int e = t; e < M * nw; e += 256) {
            int i = e / nw, w = e % nw;
            float4 bi = sBoxS[i];
            float areaA = fmaxf(bi.z - bi.x, 0.0f) * fmaxf(bi.w - bi.y, 0.0f);
            unsigned bits = 0;
            int jbase = w << 5;
            #pragma unroll 8
            for (int b = 0; b < 32; b++) {
                int j = jbase + b;
                if (j < M && j > i) {
                    float4 bj = sBoxS[j];
                    float x0 = fmaxf(bi.x, bj.x), y0 = fmaxf(bi.y, bj.y);
                    float x1 = fminf(bi.z, bj.z), y1 = fminf(bi.w, bj.w);
                    float inter = fmaxf(x1 - x0, 0.0f) * fmaxf(y1 - y0, 0.0f);
                    float areaB = fmaxf(bj.z - bj.x, 0.0f) * fmaxf(bj.w - bj.y, 0.0f);
                    float v = inter / fmaxf(areaA + areaB - inter, 1e-6f);
                    if (v > 0.7f) bits |= (1u << b);
                }
            }
            sMat[i][w] = bits;
        }
        __syncthreads();

        // serial greedy scan
        if (t == 0) {
            unsigned alive[MCAP / 32];
            #pragma unroll
            for (int w = 0; w < MCAP / 32; w++) {
                int lo32 = w << 5;
                if (M >= lo32 + 32) alive[w] = 0xFFFFFFFFu;
                else if (M <= lo32) alive[w] = 0u;
                else alive[w] = (1u << (M - lo32)) - 1u;
            }
            int cnt = 0;
            int nwv = (M + 31) >> 5;
            for (int i = 0; i < M; i++) {
                if (!((alive[i >> 5] >> (i & 31)) & 1u)) continue;
                sKeepList[cnt++] = (short)i;
                for (int w = 0; w < nwv; w++) alive[w] &= ~sMat[i][w];
            }
            sCnt = cnt;
        }
        __syncthreads();
        for (int r = t; r < sCnt; r += 256)
            sKO[sOrder[sKeepList[r]]] = 1;
        __syncthreads();
    } else {
        // Fallback (M > 256, practically unreachable): rank over global iou.
        for (int s0 = t; s0 < M; s0 += 256) {
            // recompute compaction deterministically: s0-th valid index
            int seen = -1, i = -1;
            for (int q = 0; q < NM; q++) { if (g_valid[q]) { if (++seen == s0) { i = q; break; } } }
            float ki = iou[i];
            int rank = 0;
            for (int u = 0; u < NM; u++) {
                if (!g_valid[u]) continue;
                float kj = iou[u];
                rank += (kj > ki) || (kj == ki && u < i);
            }
            sOrder[rank] = (short)i;
        }
        __syncthreads();
        if (t < 32) {
            int lane2 = t;
            unsigned alive[(NM + 1023) / 1024 * 32 / 32];
            // 1024 slots / 32 lanes = 32 bits per lane
            unsigned al = 0;
            #pragma unroll
            for (int b = 0; b < 32; b++)
                if (b * 32 + lane2 < M) al |= (1u << b);
            unsigned keepbits = 0;
            while (true) {
                int cand = al ? ((__ffs(al) - 1) * 32 + lane2) : 0x7FFFFFFF;
                #pragma unroll
                for (int off = 16; off; off >>= 1)
                    cand = min(cand, __shfl_xor_sync(0xFFFFFFFFu, cand, off));
                if (cand == 0x7FFFFFFF) break;
                int i = cand;
                if ((i & 31) == lane2) {
                    keepbits |= (1u << (i >> 5));
                    al &= ~(1u << (i >> 5));
                }
                int oi = sOrder[i];
                float4 bi = make_float4(g_boxes[oi * 4 + 0], g_boxes[oi * 4 + 1],
                                        g_boxes[oi * 4 + 2], g_boxes[oi * 4 + 3]);
                float areaA = fmaxf(bi.z - bi.x, 0.0f) * fmaxf(bi.w - bi.y, 0.0f);
                unsigned m = al;
                while (m) {
                    int b = __ffs(m) - 1; m &= m - 1;
                    int oj = sOrder[b * 32 + lane2];
                    float4 bj = make_float4(g_boxes[oj * 4 + 0], g_boxes[oj * 4 + 1],
                                            g_boxes[oj * 4 + 2], g_boxes[oj * 4 + 3]);
                    float x0 = fmaxf(bi.x, bj.x), y0 = fmaxf(bi.y, bj.y);
                    float x1 = fminf(bi.z, bj.z), y1 = fminf(bi.w, bj.w);
                    float inter = fmaxf(x1 - x0, 0.0f) * fmaxf(y1 - y0, 0.0f);
                    float areaB = fmaxf(bj.z - bj.x, 0.0f) * fmaxf(bj.w - bj.y, 0.0f);
                    float v = inter / fmaxf(areaA + areaB - inter, 1e-6f);
                    if (v > 0.7f) al &= ~(1u << b);
                }
            }
            while (keepbits) {
                int b = __ffs(keepbits) - 1; keepbits &= keepbits - 1;
                sKO[sOrder[b * 32 + lane2]] = 1;
            }
        }
        __syncthreads();
    }

    // publish gated values + tail outputs
    size_t base = (size_t)NM * HWsz;
    for (int i = t; i < NM; i += 256) {
        float k = sKO[i] ? 1.0f : 0.0f;
        g_gated[i] = k * iou[i];
        if (write_tail) {
            out[base + i] = k;
            out[base + NM + (size_t)i * 4 + 0] = g_boxes[i * 4 + 0];
            out[base + NM + (size_t)i * 4 + 1] = g_boxes[i * 4 + 1];
            out[base + NM + (size_t)i * 4 + 2] = g_boxes[i * 4 + 2];
            out[base + NM + (size_t)i * 4 + 3] = g_boxes[i * 4 + 3];
        }
    }
}

// ---------------------------------------------------------------------------
// Kernel C: VALID masks only (kept -> sigmoid*g; suppressed -> zeros).
// grid (16, NM); invalid-mask blocks exit immediately (~88%).
// ---------------------------------------------------------------------------
__global__ __launch_bounds__(256) void validout_kernel(const float* __restrict__ logits,
                                                       float* __restrict__ out) {
    int n = blockIdx.y;
    if (!g_valid[n]) return;
    float g = g_gated[n];
    size_t base = (size_t)n * HWsz;
    int i0 = blockIdx.x * 1024 + threadIdx.x;
    float4* o = (float4*)(out + base);
    if (g == 0.0f) {
        float4 z = make_float4(0.0f, 0.0f, 0.0f, 0.0f);
        #pragma unroll
        for (int j = 0; j < 4; j++) __stcs(&o[i0 + j * 256], z);
        return;
    }
    const float4* p = (const float4*)(logits + base);
    float4 v[4];
    #pragma unroll
    for (int j = 0; j < 4; j++) v[j] = __ldcs(&p[i0 + j * 256]);
    #pragma unroll
    for (int j = 0; j < 4; j++) {
        v[j].x = g / (1.0f + __expf(-v[j].x));
        v[j].y = g / (1.0f + __expf(-v[j].y));
        v[j].z = g / (1.0f + __expf(-v[j].z));
        v[j].w = g / (1.0f + __expf(-v[j].w));
        __stcs(&o[i0 + j * 256], v[j]);
    }
}

extern "C" void kernel_launch(void* const* d_in, const int* in_sizes, int n_in,
                              void* d_out, int out_size) {
    const float* logits = (const float*)d_in[0];  // [1024,256,256]
    const float* iou    = (const float*)d_in[1];  // [1024]
    float* out = (float*)d_out;

    int write_tail = (out_size >= NM * HWsz + NM + NM * 4) ? 1 : 0;

    stats_kernel<<<NM, 256>>>(logits, iou);
    nmszero_kernel<<<NM + 1, 256>>>(iou, out, write_tail);
    dim3 grid(16, NM);
    validout_kernel<<<grid, 256>>>(logits, out);
}